// round 3
// baseline (speedup 1.0000x reference)
#include <cuda_runtime.h>

// Fused depthwise 1D conv: (5-tap FD 2nd-deriv) o (9-tap Gaussian) == one 13-tap
// valid correlation per row. x: [32 rows, T=1048576] fp32 -> out: [32, T-12].
// SEG=32 outputs/thread: 11 float4 loads (44 in) -> 8 float4 stores (32 out),
// load redundancy 1.375x (vs 1.75x at SEG=16) to relieve the L1tex bottleneck.

#define T_LEN 1048576
#define L_OUT (T_LEN - 12)           // 1048564
#define SEG 32                       // outputs per thread
#define SEGS_PER_ROW (T_LEN / SEG)   // 32768
#define N_ROWS 32

__global__ __launch_bounds__(256, 2)
void fused_conv13_seg32_kernel(const float* __restrict__ x,
                               const float* __restrict__ fd,
                               const float* __restrict__ gs,
                               float* __restrict__ out)
{
    __shared__ float c_sh[13];
    const int tid = threadIdx.x;

    // Combined 13-tap kernel: c[k] = sum_{i+j=k} fd[i]*gs[j]
    if (tid < 13) {
        float acc = 0.f;
        #pragma unroll
        for (int i = 0; i < 5; ++i) {
            int j = tid - i;
            if (j >= 0 && j < 9) acc += fd[i] * gs[j];
        }
        c_sh[tid] = acc;
    }
    __syncthreads();

    float cc[13];
    #pragma unroll
    for (int k = 0; k < 13; ++k) cc[k] = c_sh[k];

    const unsigned sg  = blockIdx.x * blockDim.x + tid;   // global segment id
    const unsigned row = sg >> 15;                        // 32768 segs per row
    const unsigned seg = sg & 32767u;
    const unsigned t0  = seg * SEG;

    const float* __restrict__ xr   = x   + (size_t)row * T_LEN;
    float*       __restrict__ orow = out + (size_t)row * L_OUT;

    // 44-float sliding window covers 32 outputs of a 13-tap filter.
    // All chunks 16B-aligned; T%4==0 and L_OUT%4==0 => whole-chunk predication.
    float xin[44];
    #pragma unroll
    for (int i = 0; i < 11; ++i) {
        const unsigned p = t0 + i * 4u;
        float4 v;
        if (p < T_LEN) {
            v = *reinterpret_cast<const float4*>(xr + p);
        } else {
            v = make_float4(0.f, 0.f, 0.f, 0.f);
        }
        xin[i*4+0] = v.x; xin[i*4+1] = v.y; xin[i*4+2] = v.z; xin[i*4+3] = v.w;
    }

    #pragma unroll
    for (int j = 0; j < 8; ++j) {
        const unsigned p = t0 + j * 4u;
        if (p < L_OUT) {
            float a0 = 0.f, a1 = 0.f, a2 = 0.f, a3 = 0.f;
            #pragma unroll
            for (int k = 0; k < 13; ++k) {
                const float ck = cc[k];
                a0 = fmaf(ck, xin[j*4 + 0 + k], a0);
                a1 = fmaf(ck, xin[j*4 + 1 + k], a1);
                a2 = fmaf(ck, xin[j*4 + 2 + k], a2);
                a3 = fmaf(ck, xin[j*4 + 3 + k], a3);
            }
            float4 r; r.x = a0; r.y = a1; r.z = a2; r.w = a3;
            __stcs(reinterpret_cast<float4*>(orow + p), r);   // streaming store
        }
    }
}

extern "C" void kernel_launch(void* const* d_in, const int* in_sizes, int n_in,
                              void* d_out, int out_size)
{
    const float* x  = (const float*)d_in[0];   // [8,4,1048576]
    const float* fd = (const float*)d_in[1];   // [5]
    const float* gs = (const float*)d_in[2];   // [9]
    float* out = (float*)d_out;                // [8,4,1048564]

    const int threads = 256;
    const int total_segs = N_ROWS * SEGS_PER_ROW;      // 32 * 32768 = 1048576 threads
    const int blocks = total_segs / threads;           // 4096

    fused_conv13_seg32_kernel<<<blocks, threads>>>(x, fd, gs, out);
}

// round 7
// speedup vs baseline: 2.5942x; 2.5942x over previous
#include <cuda_runtime.h>

// Fused depthwise 1D conv: (5-tap FD) o (9-tap Gauss) == one 13-tap valid
// correlation. x: [32 rows, T=1048576] f32 -> out: [32, 1048564].
//
// SEG=4: thread t computes outputs [4t, 4t+4) of its row. Lane stride = 16B,
// so every LDG.128 / STG.128 is fully coalesced (4 wavefronts/instr, minimal).
// The 4x window overlap between adjacent threads is absorbed by L1 hits;
// DRAM traffic stays at 1 read + 1 write of the tensor. 16-float window
// [p, p+16) exactly covers 4 outputs of a 13-tap filter; max p = L_OUT-4
// gives p+16 = T_LEN, so loads are never out of bounds (no predication).

#define T_LEN 1048576
#define L_OUT (T_LEN - 12)           // 1048564
#define CHUNKS_PER_ROW (L_OUT / 4)   // 262141
#define THREADS 256
#define BLOCKS_X ((CHUNKS_PER_ROW + THREADS - 1) / THREADS)  // 1024

__global__ __launch_bounds__(THREADS)
void fused_conv13_seg4_kernel(const float* __restrict__ x,
                              const float* __restrict__ fd,
                              const float* __restrict__ gs,
                              float* __restrict__ out)
{
    __shared__ float c_sh[13];
    const int tid = threadIdx.x;

    // Combined 13-tap kernel: c[k] = sum_{i+j=k} fd[i]*gs[j]
    if (tid < 13) {
        float acc = 0.f;
        #pragma unroll
        for (int i = 0; i < 5; ++i) {
            int j = tid - i;
            if (j >= 0 && j < 9) acc += fd[i] * gs[j];
        }
        c_sh[tid] = acc;
    }
    __syncthreads();

    const unsigned chunk = blockIdx.x * THREADS + tid;   // chunk within row
    const unsigned row   = blockIdx.y;
    const unsigned p     = chunk * 4u;                   // output start index

    if (p >= L_OUT) return;

    float cc[13];
    #pragma unroll
    for (int k = 0; k < 13; ++k) cc[k] = c_sh[k];

    const float* __restrict__ xr   = x   + (size_t)row * T_LEN + p;
    float*       __restrict__ orow = out + (size_t)row * L_OUT + p;

    // 16 input floats, 4 coalesced LDG.128 (no bounds check needed: p+16 <= T_LEN)
    float xin[16];
    #pragma unroll
    for (int i = 0; i < 4; ++i) {
        float4 v = *reinterpret_cast<const float4*>(xr + i * 4);
        xin[i*4+0] = v.x; xin[i*4+1] = v.y; xin[i*4+2] = v.z; xin[i*4+3] = v.w;
    }

    float a0 = 0.f, a1 = 0.f, a2 = 0.f, a3 = 0.f;
    #pragma unroll
    for (int k = 0; k < 13; ++k) {
        const float ck = cc[k];
        a0 = fmaf(ck, xin[k + 0], a0);
        a1 = fmaf(ck, xin[k + 1], a1);
        a2 = fmaf(ck, xin[k + 2], a2);
        a3 = fmaf(ck, xin[k + 3], a3);
    }

    float4 r; r.x = a0; r.y = a1; r.z = a2; r.w = a3;
    *reinterpret_cast<float4*>(orow) = r;   // fully coalesced STG.128
}

extern "C" void kernel_launch(void* const* d_in, const int* in_sizes, int n_in,
                              void* d_out, int out_size)
{
    const float* x  = (const float*)d_in[0];   // [8,4,1048576]
    const float* fd = (const float*)d_in[1];   // [5]
    const float* gs = (const float*)d_in[2];   // [9]
    float* out = (float*)d_out;                // [8,4,1048564]

    dim3 grid(BLOCKS_X, 32, 1);
    fused_conv13_seg4_kernel<<<grid, THREADS>>>(x, fd, gs, out);
}